// round 1
// baseline (speedup 1.0000x reference)
#include <cuda_runtime.h>
#include <cuda_bf16.h>

// ---------------------------------------------------------------------------
// Problem constants
// ---------------------------------------------------------------------------
static constexpr int N_USER  = 100000;
static constexpr int N_MOVIE = 20000;
static constexpr int D_IN    = 64;
static constexpr int HID     = 128;
static constexpr int OUT     = 64;
static constexpr int E_EDGES = 600000;

// ---------------------------------------------------------------------------
// Scratch arena (single __device__ global; no allocations anywhere)
// Layout (floats):
//   [0)               deg/inv_deg user        (N_USER)
//   [OFF_DEG_M)       deg/inv_deg movie       (N_MOVIE)
//   [OFF_AGG_U1)      agg movie->user, D=64   (N_USER*64)
//   [OFF_AGG_M)       agg user->movie, D=64   (N_MOVIE*64)
//   [OFF_AGG_U3)      agg movie->user, D=128  (N_USER*128)
//   --- everything above must be zeroed each call ---
//   [OFF_USER_H)      conv1 output            (N_USER*128)
//   [OFF_MOVIE_H)     conv2 output            (N_MOVIE*128)
//   [OFF_USER_H2)     conv3 output            (N_USER*128)
// ---------------------------------------------------------------------------
static constexpr long OFF_DEG_U   = 0;
static constexpr long OFF_DEG_M   = OFF_DEG_U  + N_USER;                 // 100000
static constexpr long OFF_AGG_U1  = OFF_DEG_M  + N_MOVIE;                // 120000
static constexpr long OFF_AGG_M   = OFF_AGG_U1 + (long)N_USER * D_IN;    // 6520000
static constexpr long OFF_AGG_U3  = OFF_AGG_M  + (long)N_MOVIE * D_IN;   // 7800000
static constexpr long ZERO_FLOATS = OFF_AGG_U3 + (long)N_USER * HID;     // 20600000
static constexpr long OFF_USER_H  = ZERO_FLOATS;
static constexpr long OFF_MOVIE_H = OFF_USER_H  + (long)N_USER * HID;
static constexpr long OFF_USER_H2 = OFF_MOVIE_H + (long)N_MOVIE * HID;
static constexpr long TOTAL_FLOATS = OFF_USER_H2 + (long)N_USER * HID;

__device__ float g_scratch[TOTAL_FLOATS];

// ---------------------------------------------------------------------------
// Zero kernel (vectorized)
// ---------------------------------------------------------------------------
__global__ void zero_kernel(float4* __restrict__ p, int n4) {
    int i = blockIdx.x * blockDim.x + threadIdx.x;
    if (i < n4) p[i] = make_float4(0.f, 0.f, 0.f, 0.f);
}

// ---------------------------------------------------------------------------
// Degree computation + inversion
// ---------------------------------------------------------------------------
__global__ void degree_kernel(const int* __restrict__ eu, const int* __restrict__ em,
                              float* __restrict__ deg_u, float* __restrict__ deg_m, int E) {
    int i = blockIdx.x * blockDim.x + threadIdx.x;
    if (i < E) {
        atomicAdd(&deg_u[eu[i]], 1.0f);
        atomicAdd(&deg_m[em[i]], 1.0f);
    }
}

__global__ void invert_kernel(float* __restrict__ d, int n) {
    int i = blockIdx.x * blockDim.x + threadIdx.x;
    if (i < n) d[i] = 1.0f / fmaxf(d[i], 1.0f);
}

// ---------------------------------------------------------------------------
// Edge scatter-add: agg[dst[e]] += feat[src[e]]  (D floats per row)
// One thread handles one 16-byte chunk of one edge; vector red to L2.
// ---------------------------------------------------------------------------
__device__ __forceinline__ void red_add_v4(float* addr, float4 v) {
    asm volatile("red.global.add.v4.f32 [%0], {%1, %2, %3, %4};"
                 :: "l"(addr), "f"(v.x), "f"(v.y), "f"(v.z), "f"(v.w)
                 : "memory");
}

template <int D>
__global__ void scatter_add_kernel(const float* __restrict__ feat,
                                   const int* __restrict__ src,
                                   const int* __restrict__ dst,
                                   float* __restrict__ agg, int E) {
    constexpr int CH = D / 4;                    // float4 chunks per row
    const long total = (long)E * CH;
    for (long idx = (long)blockIdx.x * blockDim.x + threadIdx.x; idx < total;
         idx += (long)gridDim.x * blockDim.x) {
        const int e = (int)(idx / CH);
        const int c = (int)(idx % CH);
        const int s = __ldg(&src[e]);
        const int d = __ldg(&dst[e]);
        const float4 v = __ldg(reinterpret_cast<const float4*>(feat + (size_t)s * D) + c);
        red_add_v4(agg + (size_t)d * D + (size_t)c * 4, v);
    }
}

// ---------------------------------------------------------------------------
// Fused SAGE GEMM:
//   DUAL:  C = act( (A1 * invdeg[row]) @ W1 + A2 @ W2 + bias )
//   !DUAL: C = act( A1 @ W1 + bias )
// BM=128 rows per block, full N columns, 256 threads, TM=8 x TN=N/16 micro-tile
// with strided (xor-free, conflict-free) smem access + coalesced C stores.
// ---------------------------------------------------------------------------
template <int K, int N, bool DUAL, bool RELU>
__global__ __launch_bounds__(256, 2)
void sage_gemm(const float* __restrict__ A1,
               const float* __restrict__ invdeg,
               const float* __restrict__ A2,
               const float* __restrict__ W1,
               const float* __restrict__ W2,
               const float* __restrict__ bias,
               float* __restrict__ C, int M) {
    constexpr int BM = 128, BK = 8;
    constexpr int TM = 8, TN = N / 16;

    __shared__ float sA[BK][BM];
    __shared__ float sW[BK][N];

    const int tid  = threadIdx.x;
    const int tx   = tid & 15;   // column group (16 groups)
    const int ty   = tid >> 4;   // row group (16 groups)
    const int row0 = blockIdx.x * BM;

    float acc[TM][TN];
#pragma unroll
    for (int i = 0; i < TM; ++i)
#pragma unroll
        for (int j = 0; j < TN; ++j) acc[i][j] = 0.f;

    const int nMat = DUAL ? 2 : 1;
    for (int mat = 0; mat < nMat; ++mat) {
        const float* __restrict__ A = (mat == 0) ? A1 : A2;
        const float* __restrict__ W = (mat == 0) ? W1 : W2;
        for (int k0 = 0; k0 < K; k0 += BK) {
            __syncthreads();
            // --- load A tile (BM x BK), fold 1/deg into the agg operand ---
#pragma unroll
            for (int i = 0; i < (BM * BK) / 256; ++i) {
                const int idx = tid + i * 256;
                const int m = idx >> 3;
                const int k = idx & 7;
                const int gm = row0 + m;
                float v = 0.f;
                if (gm < M) {
                    v = __ldg(&A[(size_t)gm * K + k0 + k]);
                    if (DUAL && mat == 0) v *= __ldg(&invdeg[gm]);
                }
                sA[k][m] = v;
            }
            // --- load W tile (BK x N) ---
#pragma unroll
            for (int i = 0; i < (BK * N) / 256; ++i) {
                const int idx = tid + i * 256;
                const int k = idx / N;
                const int n = idx % N;
                sW[k][n] = __ldg(&W[(size_t)(k0 + k) * N + n]);
            }
            __syncthreads();
            // --- compute ---
#pragma unroll
            for (int k = 0; k < BK; ++k) {
                float aF[TM], wF[TN];
#pragma unroll
                for (int i = 0; i < TM; ++i) aF[i] = sA[k][ty + i * 16];
#pragma unroll
                for (int j = 0; j < TN; ++j) wF[j] = sW[k][tx + j * 16];
#pragma unroll
                for (int i = 0; i < TM; ++i)
#pragma unroll
                    for (int j = 0; j < TN; ++j)
                        acc[i][j] = fmaf(aF[i], wF[j], acc[i][j]);
            }
        }
    }

    // --- epilogue: bias (+ relu), coalesced stores ---
#pragma unroll
    for (int i = 0; i < TM; ++i) {
        const int gm = row0 + ty + i * 16;
        if (gm >= M) continue;
#pragma unroll
        for (int j = 0; j < TN; ++j) {
            const int gn = tx + j * 16;
            float v = acc[i][j] + __ldg(&bias[gn]);
            if (RELU) v = fmaxf(v, 0.f);
            C[(size_t)gm * N + gn] = v;
        }
    }
}

// ---------------------------------------------------------------------------
// kernel_launch
// Input order (metadata): x_user, x_movie, edge_user, edge_movie,
//   W1l, W1r, b1, W2l, W2r, b2, W3l, W3r, b3, Wlin1, blin1, Wlin2, blin2
// Output: concat(out_user [N_USER,64], out_movie [N_MOVIE,64])
// ---------------------------------------------------------------------------
extern "C" void kernel_launch(void* const* d_in, const int* in_sizes, int n_in,
                              void* d_out, int out_size) {
    const float* x_user  = (const float*)d_in[0];
    const float* x_movie = (const float*)d_in[1];
    const int*   e_user  = (const int*)d_in[2];
    const int*   e_movie = (const int*)d_in[3];
    const float* W1l = (const float*)d_in[4];
    const float* W1r = (const float*)d_in[5];
    const float* b1  = (const float*)d_in[6];
    const float* W2l = (const float*)d_in[7];
    const float* W2r = (const float*)d_in[8];
    const float* b2  = (const float*)d_in[9];
    const float* W3l = (const float*)d_in[10];
    const float* W3r = (const float*)d_in[11];
    const float* b3  = (const float*)d_in[12];
    const float* Wlin1 = (const float*)d_in[13];
    const float* blin1 = (const float*)d_in[14];
    const float* Wlin2 = (const float*)d_in[15];
    const float* blin2 = (const float*)d_in[16];

    float* scratch = nullptr;
    cudaGetSymbolAddress((void**)&scratch, g_scratch);

    float* deg_u   = scratch + OFF_DEG_U;
    float* deg_m   = scratch + OFF_DEG_M;
    float* agg_u1  = scratch + OFF_AGG_U1;
    float* agg_m   = scratch + OFF_AGG_M;
    float* agg_u3  = scratch + OFF_AGG_U3;
    float* user_h  = scratch + OFF_USER_H;
    float* movie_h = scratch + OFF_MOVIE_H;
    float* user_h2 = scratch + OFF_USER_H2;

    float* out_user  = (float*)d_out;
    float* out_movie = (float*)d_out + (size_t)N_USER * OUT;

    const int T = 256;

    // 1) zero the accumulators + degree buffers
    {
        const int n4 = (int)(ZERO_FLOATS / 4);
        zero_kernel<<<(n4 + T - 1) / T, T>>>((float4*)scratch, n4);
    }

    // 2) degrees -> inverse degrees
    degree_kernel<<<(E_EDGES + T - 1) / T, T>>>(e_user, e_movie, deg_u, deg_m, E_EDGES);
    invert_kernel<<<(N_USER + T - 1) / T, T>>>(deg_u, N_USER);
    invert_kernel<<<(N_MOVIE + T - 1) / T, T>>>(deg_m, N_MOVIE);

    // 3) conv1 aggregation: agg_u1[eu] += x_movie[em]
    {
        const long total = (long)E_EDGES * (D_IN / 4);
        scatter_add_kernel<D_IN><<<(int)((total + T - 1) / T), T>>>(
            x_movie, e_movie, e_user, agg_u1, E_EDGES);
    }
    // 4) conv1 GEMM: user_h = relu(agg_u1/deg_u @ W1l + x_user @ W1r + b1)
    sage_gemm<D_IN, HID, true, true><<<(N_USER + 127) / 128, 256>>>(
        agg_u1, deg_u, x_user, W1l, W1r, b1, user_h, N_USER);

    // 5) conv2 aggregation: agg_m[em] += x_user[eu]
    {
        const long total = (long)E_EDGES * (D_IN / 4);
        scatter_add_kernel<D_IN><<<(int)((total + T - 1) / T), T>>>(
            x_user, e_user, e_movie, agg_m, E_EDGES);
    }
    // 6) conv2 GEMM: movie_h = relu(agg_m/deg_m @ W2l + x_movie @ W2r + b2)
    sage_gemm<D_IN, HID, true, true><<<(N_MOVIE + 127) / 128, 256>>>(
        agg_m, deg_m, x_movie, W2l, W2r, b2, movie_h, N_MOVIE);

    // 7) conv3 aggregation: agg_u3[eu] += movie_h[em]   (D=128)
    {
        const long total = (long)E_EDGES * (HID / 4);
        scatter_add_kernel<HID><<<(int)((total + T - 1) / T), T>>>(
            movie_h, e_movie, e_user, agg_u3, E_EDGES);
    }
    // 8) conv3 GEMM: user_h2 = relu(agg_u3/deg_u @ W3l + user_h @ W3r + b3)
    sage_gemm<HID, HID, true, true><<<(N_USER + 127) / 128, 256>>>(
        agg_u3, deg_u, user_h, W3l, W3r, b3, user_h2, N_USER);

    // 9) linear heads (no relu)
    sage_gemm<HID, OUT, false, false><<<(N_USER + 127) / 128, 256>>>(
        user_h2, nullptr, nullptr, Wlin1, nullptr, blin1, out_user, N_USER);
    sage_gemm<HID, OUT, false, false><<<(N_MOVIE + 127) / 128, 256>>>(
        movie_h, nullptr, nullptr, Wlin2, nullptr, blin2, out_movie, N_MOVIE);

    (void)in_sizes; (void)n_in; (void)out_size;
}

// round 2
// speedup vs baseline: 1.3131x; 1.3131x over previous
#include <cuda_runtime.h>
#include <cuda_bf16.h>

// ---------------------------------------------------------------------------
// Problem constants
// ---------------------------------------------------------------------------
static constexpr int N_USER  = 100000;
static constexpr int N_MOVIE = 20000;
static constexpr int D_IN    = 64;
static constexpr int HID     = 128;
static constexpr int OUT     = 64;
static constexpr int E_EDGES = 600000;

// ---------------------------------------------------------------------------
// Static scratch (no allocations anywhere). ~205 MB total.
// ---------------------------------------------------------------------------
__device__ int g_cnt_u[N_USER];
__device__ int g_cnt_m[N_MOVIE];
__device__ int g_off_u[N_USER + 1];
__device__ int g_off_m[N_MOVIE + 1];
__device__ int g_cur_u[N_USER];
__device__ int g_cur_m[N_MOVIE];
__device__ int g_csr_u[E_EDGES];      // movie src indices grouped by user dst
__device__ int g_csr_m[E_EDGES];      // user  src indices grouped by movie dst
__device__ int g_part_u[1024];
__device__ int g_part_m[1024];

__device__ __align__(256) float g_agg_u1[(size_t)N_USER  * D_IN];
__device__ __align__(256) float g_agg_m [(size_t)N_MOVIE * D_IN];
__device__ __align__(256) float g_agg_u3[(size_t)N_USER  * HID];
__device__ __align__(256) float g_user_h [(size_t)N_USER  * HID];
__device__ __align__(256) float g_movie_h[(size_t)N_MOVIE * HID];
__device__ __align__(256) float g_user_h2[(size_t)N_USER  * HID];

// ---------------------------------------------------------------------------
// CSR build: histogram -> exclusive scan -> cursor fill
// ---------------------------------------------------------------------------
__global__ void zero_counts_kernel(int* __restrict__ cu, int* __restrict__ cm) {
    int i = blockIdx.x * blockDim.x + threadIdx.x;
    if (i < N_USER) cu[i] = 0;
    if (i < N_MOVIE) cm[i] = 0;
}

__global__ void count_kernel(const int* __restrict__ eu, const int* __restrict__ em,
                             int* __restrict__ cu, int* __restrict__ cm, int E) {
    int i = blockIdx.x * blockDim.x + threadIdx.x;
    if (i < E) {
        atomicAdd(&cu[__ldg(&eu[i])], 1);
        atomicAdd(&cm[__ldg(&em[i])], 1);
    }
}

// Per-block exclusive scan; block totals to partial[].
__global__ void scan_block_kernel(const int* __restrict__ cnt, int* __restrict__ excl,
                                  int* __restrict__ partial, int n) {
    __shared__ int warp_sums[32];
    const int tid  = threadIdx.x;
    const int lane = tid & 31;
    const int wid  = tid >> 5;
    const int gid  = blockIdx.x * 1024 + tid;

    int v = (gid < n) ? cnt[gid] : 0;
    int x = v;
#pragma unroll
    for (int o = 1; o < 32; o <<= 1) {
        int y = __shfl_up_sync(0xFFFFFFFFu, x, o);
        if (lane >= o) x += y;
    }
    if (lane == 31) warp_sums[wid] = x;
    __syncthreads();
    if (wid == 0) {
        int s = warp_sums[lane];
#pragma unroll
        for (int o = 1; o < 32; o <<= 1) {
            int y = __shfl_up_sync(0xFFFFFFFFu, s, o);
            if (lane >= o) s += y;
        }
        warp_sums[lane] = s;
    }
    __syncthreads();
    const int base = (wid > 0) ? warp_sums[wid - 1] : 0;
    const int incl = base + x;
    if (gid < n) excl[gid] = incl - v;
    if (tid == 1023) partial[blockIdx.x] = incl;  // block total (padding = 0)
}

// Single-block exclusive scan of partial[] (nb <= 1024).
__global__ void scan_partial_kernel(int* __restrict__ partial, int nb) {
    __shared__ int warp_sums[32];
    const int tid  = threadIdx.x;
    const int lane = tid & 31;
    const int wid  = tid >> 5;
    int v = (tid < nb) ? partial[tid] : 0;
    int x = v;
#pragma unroll
    for (int o = 1; o < 32; o <<= 1) {
        int y = __shfl_up_sync(0xFFFFFFFFu, x, o);
        if (lane >= o) x += y;
    }
    if (lane == 31) warp_sums[wid] = x;
    __syncthreads();
    if (wid == 0) {
        int s = warp_sums[lane];
#pragma unroll
        for (int o = 1; o < 32; o <<= 1) {
            int y = __shfl_up_sync(0xFFFFFFFFu, s, o);
            if (lane >= o) s += y;
        }
        warp_sums[lane] = s;
    }
    __syncthreads();
    const int base = (wid > 0) ? warp_sums[wid - 1] : 0;
    if (tid < nb) partial[tid] = base + x - v;    // exclusive
}

// Add block offsets; also seed cursor copy and the sentinel off[n] = E.
__global__ void scan_finalize_kernel(int* __restrict__ off, int* __restrict__ cur,
                                     const int* __restrict__ partial, int n, int E) {
    const int gid = blockIdx.x * 1024 + threadIdx.x;
    if (gid < n) {
        const int o = off[gid] + partial[blockIdx.x];
        off[gid] = o;
        cur[gid] = o;
    }
    if (gid == 0) off[n] = E;
}

__global__ void fill_kernel(const int* __restrict__ eu, const int* __restrict__ em,
                            int* __restrict__ cur_u, int* __restrict__ cur_m,
                            int* __restrict__ csr_u, int* __restrict__ csr_m, int E) {
    int i = blockIdx.x * blockDim.x + threadIdx.x;
    if (i < E) {
        const int u = __ldg(&eu[i]);
        const int m = __ldg(&em[i]);
        csr_u[atomicAdd(&cur_u[u], 1)] = m;
        csr_m[atomicAdd(&cur_m[m], 1)] = u;
    }
}

// ---------------------------------------------------------------------------
// Warp-per-node mean gather: agg[d] = mean over edges of feat[src]
// ---------------------------------------------------------------------------
template <int D>
__global__ void gather_mean_kernel(const float* __restrict__ feat,
                                   const int* __restrict__ csr,
                                   const int* __restrict__ off,
                                   float* __restrict__ agg, int n) {
    const int warp = (blockIdx.x * blockDim.x + threadIdx.x) >> 5;
    const int lane = threadIdx.x & 31;
    if (warp >= n) return;
    const int s0 = __ldg(&off[warp]);
    const int s1 = __ldg(&off[warp + 1]);
    const float inv = 1.0f / fmaxf((float)(s1 - s0), 1.0f);

    if constexpr (D == 64) {
        float v0 = 0.f, v1 = 0.f;
        int i = s0;
        for (; i + 1 < s1; i += 2) {
            const int a = __ldg(&csr[i]);
            const int b = __ldg(&csr[i + 1]);
            const float* ra = feat + (size_t)a * 64;
            const float* rb = feat + (size_t)b * 64;
            v0 += __ldg(ra + lane)      + __ldg(rb + lane);
            v1 += __ldg(ra + lane + 32) + __ldg(rb + lane + 32);
        }
        if (i < s1) {
            const int a = __ldg(&csr[i]);
            v0 += __ldg(feat + (size_t)a * 64 + lane);
            v1 += __ldg(feat + (size_t)a * 64 + lane + 32);
        }
        agg[(size_t)warp * 64 + lane]      = v0 * inv;
        agg[(size_t)warp * 64 + lane + 32] = v1 * inv;
    } else {  // D == 128, float4 per lane
        float4 acc = make_float4(0.f, 0.f, 0.f, 0.f);
        int i = s0;
        for (; i + 1 < s1; i += 2) {
            const int a = __ldg(&csr[i]);
            const int b = __ldg(&csr[i + 1]);
            const float4 fa = __ldg(reinterpret_cast<const float4*>(feat + (size_t)a * 128) + lane);
            const float4 fb = __ldg(reinterpret_cast<const float4*>(feat + (size_t)b * 128) + lane);
            acc.x += fa.x + fb.x; acc.y += fa.y + fb.y;
            acc.z += fa.z + fb.z; acc.w += fa.w + fb.w;
        }
        if (i < s1) {
            const int a = __ldg(&csr[i]);
            const float4 fa = __ldg(reinterpret_cast<const float4*>(feat + (size_t)a * 128) + lane);
            acc.x += fa.x; acc.y += fa.y; acc.z += fa.z; acc.w += fa.w;
        }
        acc.x *= inv; acc.y *= inv; acc.z *= inv; acc.w *= inv;
        reinterpret_cast<float4*>(agg + (size_t)warp * 128)[lane] = acc;
    }
}

// ---------------------------------------------------------------------------
// Fused SAGE GEMM:
//   DUAL:  C = act( A1 @ W1 + A2 @ W2 + bias )   (A1 already mean-normalized)
//   !DUAL: C = act( A1 @ W1 + bias )
// ---------------------------------------------------------------------------
template <int K, int N, bool DUAL, bool RELU>
__global__ __launch_bounds__(256, 2)
void sage_gemm(const float* __restrict__ A1,
               const float* __restrict__ A2,
               const float* __restrict__ W1,
               const float* __restrict__ W2,
               const float* __restrict__ bias,
               float* __restrict__ C, int M) {
    constexpr int BM = 128, BK = 8;
    constexpr int TM = 8, TN = N / 16;

    __shared__ float sA[BK][BM];
    __shared__ float sW[BK][N];

    const int tid  = threadIdx.x;
    const int tx   = tid & 15;
    const int ty   = tid >> 4;
    const int row0 = blockIdx.x * BM;

    float acc[TM][TN];
#pragma unroll
    for (int i = 0; i < TM; ++i)
#pragma unroll
        for (int j = 0; j < TN; ++j) acc[i][j] = 0.f;

    const int nMat = DUAL ? 2 : 1;
    for (int mat = 0; mat < nMat; ++mat) {
        const float* __restrict__ A = (mat == 0) ? A1 : A2;
        const float* __restrict__ W = (mat == 0) ? W1 : W2;
        for (int k0 = 0; k0 < K; k0 += BK) {
            __syncthreads();
#pragma unroll
            for (int i = 0; i < (BM * BK) / 256; ++i) {
                const int idx = tid + i * 256;
                const int m = idx >> 3;
                const int k = idx & 7;
                const int gm = row0 + m;
                sA[k][m] = (gm < M) ? __ldg(&A[(size_t)gm * K + k0 + k]) : 0.f;
            }
#pragma unroll
            for (int i = 0; i < (BK * N) / 256; ++i) {
                const int idx = tid + i * 256;
                const int k = idx / N;
                const int n = idx % N;
                sW[k][n] = __ldg(&W[(size_t)(k0 + k) * N + n]);
            }
            __syncthreads();
#pragma unroll
            for (int k = 0; k < BK; ++k) {
                float aF[TM], wF[TN];
#pragma unroll
                for (int i = 0; i < TM; ++i) aF[i] = sA[k][ty + i * 16];
#pragma unroll
                for (int j = 0; j < TN; ++j) wF[j] = sW[k][tx + j * 16];
#pragma unroll
                for (int i = 0; i < TM; ++i)
#pragma unroll
                    for (int j = 0; j < TN; ++j)
                        acc[i][j] = fmaf(aF[i], wF[j], acc[i][j]);
            }
        }
    }

#pragma unroll
    for (int i = 0; i < TM; ++i) {
        const int gm = row0 + ty + i * 16;
        if (gm >= M) continue;
#pragma unroll
        for (int j = 0; j < TN; ++j) {
            const int gn = tx + j * 16;
            float v = acc[i][j] + __ldg(&bias[gn]);
            if (RELU) v = fmaxf(v, 0.f);
            C[(size_t)gm * N + gn] = v;
        }
    }
}

// ---------------------------------------------------------------------------
// kernel_launch
// ---------------------------------------------------------------------------
extern "C" void kernel_launch(void* const* d_in, const int* in_sizes, int n_in,
                              void* d_out, int out_size) {
    const float* x_user  = (const float*)d_in[0];
    const float* x_movie = (const float*)d_in[1];
    const int*   e_user  = (const int*)d_in[2];
    const int*   e_movie = (const int*)d_in[3];
    const float* W1l = (const float*)d_in[4];
    const float* W1r = (const float*)d_in[5];
    const float* b1  = (const float*)d_in[6];
    const float* W2l = (const float*)d_in[7];
    const float* W2r = (const float*)d_in[8];
    const float* b2  = (const float*)d_in[9];
    const float* W3l = (const float*)d_in[10];
    const float* W3r = (const float*)d_in[11];
    const float* b3  = (const float*)d_in[12];
    const float* Wlin1 = (const float*)d_in[13];
    const float* blin1 = (const float*)d_in[14];
    const float* Wlin2 = (const float*)d_in[15];
    const float* blin2 = (const float*)d_in[16];

    int *cnt_u, *cnt_m, *off_u, *off_m, *cur_u, *cur_m, *csr_u, *csr_m, *part_u, *part_m;
    float *agg_u1, *agg_m, *agg_u3, *user_h, *movie_h, *user_h2;
    cudaGetSymbolAddress((void**)&cnt_u, g_cnt_u);
    cudaGetSymbolAddress((void**)&cnt_m, g_cnt_m);
    cudaGetSymbolAddress((void**)&off_u, g_off_u);
    cudaGetSymbolAddress((void**)&off_m, g_off_m);
    cudaGetSymbolAddress((void**)&cur_u, g_cur_u);
    cudaGetSymbolAddress((void**)&cur_m, g_cur_m);
    cudaGetSymbolAddress((void**)&csr_u, g_csr_u);
    cudaGetSymbolAddress((void**)&csr_m, g_csr_m);
    cudaGetSymbolAddress((void**)&part_u, g_part_u);
    cudaGetSymbolAddress((void**)&part_m, g_part_m);
    cudaGetSymbolAddress((void**)&agg_u1, g_agg_u1);
    cudaGetSymbolAddress((void**)&agg_m,  g_agg_m);
    cudaGetSymbolAddress((void**)&agg_u3, g_agg_u3);
    cudaGetSymbolAddress((void**)&user_h, g_user_h);
    cudaGetSymbolAddress((void**)&movie_h, g_movie_h);
    cudaGetSymbolAddress((void**)&user_h2, g_user_h2);

    float* out_user  = (float*)d_out;
    float* out_movie = (float*)d_out + (size_t)N_USER * OUT;

    const int T = 256;
    const int Bu = (N_USER  + 1023) / 1024;   // 98
    const int Bm = (N_MOVIE + 1023) / 1024;   // 20

    // ---- CSR build (used by all three convolutions) ----
    zero_counts_kernel<<<(N_USER + T - 1) / T, T>>>(cnt_u, cnt_m);
    count_kernel<<<(E_EDGES + T - 1) / T, T>>>(e_user, e_movie, cnt_u, cnt_m, E_EDGES);
    scan_block_kernel<<<Bu, 1024>>>(cnt_u, off_u, part_u, N_USER);
    scan_block_kernel<<<Bm, 1024>>>(cnt_m, off_m, part_m, N_MOVIE);
    scan_partial_kernel<<<1, 1024>>>(part_u, Bu);
    scan_partial_kernel<<<1, 1024>>>(part_m, Bm);
    scan_finalize_kernel<<<Bu, 1024>>>(off_u, cur_u, part_u, N_USER, E_EDGES);
    scan_finalize_kernel<<<Bm, 1024>>>(off_m, cur_m, part_m, N_MOVIE, E_EDGES);
    fill_kernel<<<(E_EDGES + T - 1) / T, T>>>(e_user, e_movie, cur_u, cur_m,
                                              csr_u, csr_m, E_EDGES);

    // ---- conv1: gather x_movie per user, GEMM ----
    gather_mean_kernel<D_IN><<<(N_USER + 7) / 8, 256>>>(x_movie, csr_u, off_u, agg_u1, N_USER);
    sage_gemm<D_IN, HID, true, true><<<(N_USER + 127) / 128, 256>>>(
        agg_u1, x_user, W1l, W1r, b1, user_h, N_USER);

    // ---- conv2: gather x_user per movie, GEMM ----
    gather_mean_kernel<D_IN><<<(N_MOVIE + 7) / 8, 256>>>(x_user, csr_m, off_m, agg_m, N_MOVIE);
    sage_gemm<D_IN, HID, true, true><<<(N_MOVIE + 127) / 128, 256>>>(
        agg_m, x_movie, W2l, W2r, b2, movie_h, N_MOVIE);

    // ---- conv3: gather movie_h per user, GEMM ----
    gather_mean_kernel<HID><<<(N_USER + 7) / 8, 256>>>(movie_h, csr_u, off_u, agg_u3, N_USER);
    sage_gemm<HID, HID, true, true><<<(N_USER + 127) / 128, 256>>>(
        agg_u3, user_h, W3l, W3r, b3, user_h2, N_USER);

    // ---- linear heads ----
    sage_gemm<HID, OUT, false, false><<<(N_USER + 127) / 128, 256>>>(
        user_h2, nullptr, Wlin1, nullptr, blin1, out_user, N_USER);
    sage_gemm<HID, OUT, false, false><<<(N_MOVIE + 127) / 128, 256>>>(
        movie_h, nullptr, Wlin2, nullptr, blin2, out_movie, N_MOVIE);

    (void)in_sizes; (void)n_in; (void)out_size;
}